// round 12
// baseline (speedup 1.0000x reference)
#include <cuda_runtime.h>

#define BB  64
#define INN 512
#define HH  512
#define HID 16
#define BSPLIT 2
#define BHALF (BB / BSPLIT)

// ---------------- packed f32x2 helpers (Blackwell sm_100+) ----------------
typedef unsigned long long u64;

static __device__ __forceinline__ u64 f2_fma(u64 a, u64 b, u64 c) {
    u64 r;
    asm("fma.rn.f32x2 %0, %1, %2, %3;" : "=l"(r) : "l"(a), "l"(b), "l"(c));
    return r;
}
static __device__ __forceinline__ u64 f2_add(u64 a, u64 b) {
    u64 r;
    asm("add.rn.f32x2 %0, %1, %2;" : "=l"(r) : "l"(a), "l"(b));
    return r;
}
static __device__ __forceinline__ u64 f2_pack(float x, float y) {
    u64 r;
    asm("mov.b64 %0, {%1, %2};" : "=l"(r) : "f"(x), "f"(y));
    return r;
}
static __device__ __forceinline__ float2 f2_unpack(u64 v) {
    float2 r;
    asm("mov.b64 {%0, %1}, %2;" : "=f"(r.x), "=f"(r.y) : "l"(v));
    return r;
}
// relu: pack/unpack are register aliasing (free); 2x FMNMX on the alu pipe.
static __device__ __forceinline__ u64 f2_relu(u64 v) {
    float2 t = f2_unpack(v);
    return f2_pack(fmaxf(t.x, 0.0f), fmaxf(t.y, 0.0f));
}

// ---------------- zero-init (d_out is poisoned by the harness) ----------------
__global__ void zero_out(float4* __restrict__ out) {
    out[blockIdx.x * 256 + threadIdx.x] = make_float4(0.f, 0.f, 0.f, 0.f);
}

// ---------------- fused kernel, b-split x2 ----------------
// out[i,j] = (1/B) * sum_b sum_k relu(pre[b,i]*u_k + post[b,j]*v_k + w_ij*t_k + b1_k) * W2_k + b2
//
// R12: occupancy was GRID-limited (1024 blocks = 27.7 warps/SM) while the RF
// at 56 regs holds 9 blocks = 36 warps/SM. Split the b-reduction across
// gridDim.z = 2 -> 2048 blocks = 8192 warps; per-SM 13.8 blocks over 9 slots
// gives ~36 resident warps during the main wave and 0.77x makespan.
// Each z-half contributes via atomicAdd(float2) -- exactly 2 commutative
// contributions per output = bit-deterministic. b2 bias added by z==0 only.
// Structure otherwise = R11: 1i x 2j tile, k-quarter chunks (20 const regs),
// d-trick, b x 2 unroll with batched loads.
__global__ __launch_bounds__(128, 9)
void plasticity_fused(const float* __restrict__ pre,
                      const float* __restrict__ post,
                      const float* __restrict__ weight,
                      const float* __restrict__ W1,
                      const float* __restrict__ b1,
                      const float* __restrict__ W2,
                      const float* __restrict__ b2,
                      float* __restrict__ out) {
    const int tj = threadIdx.x & 63;       // 0..63
    const int ti = threadIdx.x >> 6;       // 0..1 (warp-uniform)
    const int i  = blockIdx.y * 2 + ti;
    const int j0 = blockIdx.x * 128 + tj * 2;
    const int b0 = blockIdx.z * BHALF;     // this block's batch range start

    // w_ij for this thread's 2 j.
    const float2 wv = *reinterpret_cast<const float2*>(&weight[(size_t)i * HH + j0]);

    // 2 jj x 2 kp accumulator chains, persist across chunks.
    u64 acc[2][2] = { {0ull, 0ull}, {0ull, 0ull} };

#pragma unroll 1
    for (int chunk = 0; chunk < 4; ++chunk) {
        const int k0 = chunk * 4;          // 4 k = 2 packed pairs per chunk
        // Live constants this chunk: 5 arrays x 2 pairs = 20 regs.
        u64 u2[2], v2[2], w2p[2], d0[2], d1[2];
        {
            const u64 wij0 = f2_pack(wv.x, wv.x);
            const u64 wij1 = f2_pack(wv.y, wv.y);
#pragma unroll
            for (int kp = 0; kp < 2; ++kp) {
                int ka = k0 + 2 * kp, kb = ka + 1;
                u2[kp]  = f2_pack(W1[ka * 3 + 0], W1[kb * 3 + 0]);
                v2[kp]  = f2_pack(W1[ka * 3 + 1], W1[kb * 3 + 1]);
                u64 t2  = f2_pack(W1[ka * 3 + 2], W1[kb * 3 + 2]);
                u64 b12 = f2_pack(b1[ka], b1[kb]);
                w2p[kp] = f2_pack(W2[ka], W2[kb]);
                d0[kp]  = f2_fma(wij0, t2, b12);   // w_i,j0   * t_k + b1_k
                d1[kp]  = f2_fma(wij1, t2, b12);   // w_i,j0+1 * t_k + b1_k
            }
        }

        const float* pp = pre  + (size_t)b0 * INN + i;   // advances 2*INN/iter
        const float* qq = post + (size_t)b0 * HH  + j0;  // advances 2*HH/iter

#pragma unroll 1
        for (int b = 0; b < BHALF; b += 2) {
            // Batch all 4 loads up front (one scoreboard wait per 2 b).
            const float  cp0 = pp[0];
            const float  cp1 = pp[INN];
            const float2 cq0 = *reinterpret_cast<const float2*>(qq);
            const float2 cq1 = *reinterpret_cast<const float2*>(qq + HH);
            pp += 2 * INN;
            qq += 2 * HH;

            // ---- b even ----
            {
                const u64 pre2  = f2_pack(cp0, cp0);
                const u64 postA = f2_pack(cq0.x, cq0.x);
                const u64 postB = f2_pack(cq0.y, cq0.y);
#pragma unroll
                for (int kp = 0; kp < 2; ++kp) {
                    u64 x0 = f2_fma(postA, v2[kp], d0[kp]);
                    x0 = f2_fma(pre2, u2[kp], x0);
                    acc[0][kp] = f2_fma(f2_relu(x0), w2p[kp], acc[0][kp]);

                    u64 x1 = f2_fma(postB, v2[kp], d1[kp]);
                    x1 = f2_fma(pre2, u2[kp], x1);
                    acc[1][kp] = f2_fma(f2_relu(x1), w2p[kp], acc[1][kp]);
                }
            }
            // ---- b odd ----
            {
                const u64 pre2  = f2_pack(cp1, cp1);
                const u64 postA = f2_pack(cq1.x, cq1.x);
                const u64 postB = f2_pack(cq1.y, cq1.y);
#pragma unroll
                for (int kp = 0; kp < 2; ++kp) {
                    u64 x0 = f2_fma(postA, v2[kp], d0[kp]);
                    x0 = f2_fma(pre2, u2[kp], x0);
                    acc[0][kp] = f2_fma(f2_relu(x0), w2p[kp], acc[0][kp]);

                    u64 x1 = f2_fma(postB, v2[kp], d1[kp]);
                    x1 = f2_fma(pre2, u2[kp], x1);
                    acc[1][kp] = f2_fma(f2_relu(x1), w2p[kp], acc[1][kp]);
                }
            }
        }
    }

    const float inv_b = 1.0f / (float)BB;
    // Bias added exactly once (by the z==0 contribution).
    const float bias2 = (blockIdx.z == 0) ? b2[0] : 0.0f;
    float2 res;
#pragma unroll
    for (int jj = 0; jj < 2; ++jj) {
        float2 s = f2_unpack(f2_add(acc[jj][0], acc[jj][1]));
        (&res.x)[jj] = fmaf(s.x + s.y, inv_b, bias2);
    }
    // Two commutative float adds per output -> deterministic result.
    atomicAdd(reinterpret_cast<float2*>(&out[(size_t)i * HH + j0]), res);
}

// ---------------- launch ----------------
extern "C" void kernel_launch(void* const* d_in, const int* in_sizes, int n_in,
                              void* d_out, int out_size) {
    const float* pre    = (const float*)d_in[0];
    const float* post   = (const float*)d_in[1];
    const float* weight = (const float*)d_in[2];
    const float* W1     = (const float*)d_in[3];
    const float* b1     = (const float*)d_in[4];
    const float* W2     = (const float*)d_in[5];
    const float* b2     = (const float*)d_in[6];
    float* out = (float*)d_out;

    // INN*HH floats = 65536 float4 -> 256 blocks x 256 threads.
    zero_out<<<INN * HH / 4 / 256, 256>>>((float4*)out);
    plasticity_fused<<<dim3(HH / 128, INN / 2, BSPLIT), 128>>>(
        pre, post, weight, W1, b1, W2, b2, out);
}

// round 13
// speedup vs baseline: 1.0532x; 1.0532x over previous
#include <cuda_runtime.h>

#define BB  64
#define INN 512
#define HH  512
#define HID 16

// ---------------- packed f32x2 helpers (Blackwell sm_100+) ----------------
typedef unsigned long long u64;

static __device__ __forceinline__ u64 f2_fma(u64 a, u64 b, u64 c) {
    u64 r;
    asm("fma.rn.f32x2 %0, %1, %2, %3;" : "=l"(r) : "l"(a), "l"(b), "l"(c));
    return r;
}
static __device__ __forceinline__ u64 f2_add(u64 a, u64 b) {
    u64 r;
    asm("add.rn.f32x2 %0, %1, %2;" : "=l"(r) : "l"(a), "l"(b));
    return r;
}
static __device__ __forceinline__ u64 f2_pack(float x, float y) {
    u64 r;
    asm("mov.b64 %0, {%1, %2};" : "=l"(r) : "f"(x), "f"(y));
    return r;
}
static __device__ __forceinline__ float2 f2_unpack(u64 v) {
    float2 r;
    asm("mov.b64 {%0, %1}, %2;" : "=f"(r.x), "=f"(r.y) : "l"(v));
    return r;
}
// relu: pack/unpack are register aliasing (free); 2x FMNMX on the alu pipe.
static __device__ __forceinline__ u64 f2_relu(u64 v) {
    float2 t = f2_unpack(v);
    return f2_pack(fmaxf(t.x, 0.0f), fmaxf(t.y, 0.0f));
}

// ---------------- fused kernel, j-paired lanes ----------------
// out[i,j] = (1/B) * sum_b sum_k relu(pre[b,i]*u_k + post[b,j]*v_k + w_ij*t_k + b1_k) * W2_k + b2
//
// R13: f32x2 lanes repacked from (k,k+1) to (j0,j0+1). Consequences:
//  - post pair & w_ij pair load DIRECTLY as 64-bit LDGs (no broadcast packs)
//  - output stores as a natural pair; k-sum accumulates in-lane
//  - k-broadcast constants (u,v,W2 pairs and d[k] = w_pair*t_k + b1_k)
//    hoist into the chunk prologue, OUT of the b-loop
//  - per-b overhead: 1 MOV + 2 LDG (was ~6 MOV + 2 LDG) -> ~13% fewer issues
// Structure otherwise = R11 (best 47.1us): 1i x 2j thread tile, k-quarter
// chunks, b x 2 unroll with batched loads, single kernel, no atomics.
// 4 direct acc chains (one per k of chunk).
__global__ __launch_bounds__(128, 8)
void plasticity_fused(const float* __restrict__ pre,
                      const float* __restrict__ post,
                      const float* __restrict__ weight,
                      const float* __restrict__ W1,
                      const float* __restrict__ b1,
                      const float* __restrict__ W2,
                      const float* __restrict__ b2,
                      float* __restrict__ out) {
    const int tj = threadIdx.x & 63;       // 0..63
    const int ti = threadIdx.x >> 6;       // 0..1 (warp-uniform)
    const int i  = blockIdx.y * 2 + ti;
    const int j0 = blockIdx.x * 128 + tj * 2;

    // w_(i,j0), w_(i,j0+1) as a natural 64-bit pair (8B-aligned: j0 even).
    const u64 wpair = *reinterpret_cast<const u64*>(&weight[(size_t)i * HH + j0]);

    // 4 accumulator chains (one per k within a chunk), lanes = (j0, j0+1).
    u64 acc[4] = { 0ull, 0ull, 0ull, 0ull };

#pragma unroll 1
    for (int chunk = 0; chunk < 4; ++chunk) {
        const int k0 = chunk * 4;
        // Per-chunk constants, all broadcast pairs hoisted out of the b-loop:
        // u_bb, v_bb, w2_bb, d = 16 pairs = 32 regs.
        u64 u_bb[4], v_bb[4], w2_bb[4], d[4];
#pragma unroll
        for (int kk = 0; kk < 4; ++kk) {
            const int k = k0 + kk;
            const float uk = W1[k * 3 + 0];
            const float vk = W1[k * 3 + 1];
            const float tk = W1[k * 3 + 2];
            u_bb[kk]  = f2_pack(uk, uk);
            v_bb[kk]  = f2_pack(vk, vk);
            w2_bb[kk] = f2_pack(W2[k], W2[k]);
            const u64 t_bb  = f2_pack(tk, tk);
            const u64 b1_bb = f2_pack(b1[k], b1[k]);
            d[kk] = f2_fma(wpair, t_bb, b1_bb);    // w_ij * t_k + b1_k (pair)
        }

        const float* pp = pre + i;                             // +2*INN per iter
        const u64*   qq = reinterpret_cast<const u64*>(post + j0);  // +HH floats per b

#pragma unroll 1
        for (int b = 0; b < BB; b += 2) {
            // Batch all 4 loads up front (one scoreboard wait per 2 b).
            const float cp0 = pp[0];
            const float cp1 = pp[INN];
            const u64   q0  = qq[0];              // (post[b,j0], post[b,j0+1])
            const u64   q1  = qq[HH / 2];         // next b row (u64 stride HH/2)
            pp += 2 * INN;
            qq += HH;                              // 2 rows of HH/2 u64

            const u64 pre0 = f2_pack(cp0, cp0);    // only pack left in the loop
            const u64 pre1 = f2_pack(cp1, cp1);

            // ---- b even ----
#pragma unroll
            for (int kk = 0; kk < 4; ++kk) {
                u64 x = f2_fma(q0, v_bb[kk], d[kk]);     // post*v + (w*t+b1)
                x = f2_fma(pre0, u_bb[kk], x);           // + pre*u
                acc[kk] = f2_fma(f2_relu(x), w2_bb[kk], acc[kk]);
            }
            // ---- b odd ----
#pragma unroll
            for (int kk = 0; kk < 4; ++kk) {
                u64 x = f2_fma(q1, v_bb[kk], d[kk]);
                x = f2_fma(pre1, u_bb[kk], x);
                acc[kk] = f2_fma(f2_relu(x), w2_bb[kk], acc[kk]);
            }
        }
    }

    // Epilogue: in-lane k-sum is already done; just combine the 4 chains,
    // scale by 1/B and add bias -- all as pairs, store 64-bit.
    const float inv_b = 1.0f / (float)BB;
    const float bias2 = b2[0];
    const u64 inv_bb  = f2_pack(inv_b, inv_b);
    const u64 bias_bb = f2_pack(bias2, bias2);
    u64 s = f2_add(f2_add(acc[0], acc[1]), f2_add(acc[2], acc[3]));
    u64 res = f2_fma(s, inv_bb, bias_bb);
    *reinterpret_cast<u64*>(&out[(size_t)i * HH + j0]) = res;
}

// ---------------- launch ----------------
extern "C" void kernel_launch(void* const* d_in, const int* in_sizes, int n_in,
                              void* d_out, int out_size) {
    const float* pre    = (const float*)d_in[0];
    const float* post   = (const float*)d_in[1];
    const float* weight = (const float*)d_in[2];
    const float* W1     = (const float*)d_in[3];
    const float* b1     = (const float*)d_in[4];
    const float* W2     = (const float*)d_in[5];
    const float* b2     = (const float*)d_in[6];
    float* out = (float*)d_out;

    plasticity_fused<<<dim3(HH / 128, INN / 2), 128>>>(
        pre, post, weight, W1, b1, W2, b2, out);
}